// round 6
// baseline (speedup 1.0000x reference)
#include <cuda_runtime.h>
#include <cuda_fp16.h>
#include <math.h>

#define NMAX 100000
#define EMAX 1600000
#define NGR  256
#define SCANB 1024

// ---------------- device scratch (allocation-free rule: __device__ globals) ----------------
__device__ __align__(16) float g_h[(size_t)NMAX * 64];     // XW result per layer (fp32)
__device__ __align__(16) __half2 g_hb[(size_t)NMAX * 32];  // fp16 copy for gather
__device__ __align__(16) float g_o[(size_t)NMAX * 64];     // aggregated output per layer
__device__ float g_deg[NMAX];
__device__ float g_dis[NMAX];
__device__ long long g_csr[EMAX];        // packed (norm<<32 | src) sorted by dst
__device__ int   g_rowptr[NMAX + 1];
__device__ int   g_cursor[NMAX];
__device__ int   g_rowtmp[NMAX];
__device__ int   g_bsum[128];
__device__ int   g_boff[128];
__device__ float g_logits[NMAX];
__device__ int   g_cnt[NGR];
__device__ int   g_is64;

// ---------------- int64/int32 index abstraction ----------------
__device__ __forceinline__ long long load_index(const void* p, long long i) {
    if (g_is64) return ((const long long*)p)[i];
    return (long long)((const int*)p)[i];
}

// Detect dtype of edge_index: node ids < 2^17, so for int64 every high word is 0.
__global__ void k_detect(const unsigned int* w, long long nvals) {
    __shared__ int any;
    if (threadIdx.x == 0) any = 0;
    __syncthreads();
    long long lim = nvals < 512 ? nvals : 512;
    for (long long i = threadIdx.x; i < lim; i += blockDim.x)
        if (w[2 * i + 1] != 0u) any = 1;
    __syncthreads();
    if (threadIdx.x == 0) g_is64 = (any == 0) ? 1 : 0;
}

__global__ void k_init(int n) {
    int i = blockIdx.x * blockDim.x + threadIdx.x;
    if (i < n) g_deg[i] = 1.0f;   // self loop
    if (i < NGR) g_cnt[i] = 0;
}

__global__ void k_count(const void* ei, int nE) {
    int e = blockIdx.x * blockDim.x + threadIdx.x;
    if (e >= nE) return;
    int d = (int)load_index(ei, (long long)nE + e);
    atomicAdd(&g_deg[d], 1.0f);
}

// dis + block-level exclusive scan (stage 1) over int dst-counts ((int)deg - 1, exact)
__global__ void k_dis_scan1(int n) {
    __shared__ int sh[2][SCANB];
    int t = threadIdx.x;
    int i = blockIdx.x * SCANB + t;
    int c = 0;
    if (i < n) {
        float dv = g_deg[i];
        g_dis[i] = rsqrtf(dv);
        c = (int)dv - 1;
    }
    sh[0][t] = c;
    __syncthreads();
    int src = 0;
    for (int off = 1; off < SCANB; off <<= 1) {
        int v = sh[src][t];
        if (t >= off) v += sh[src][t - off];
        sh[src ^ 1][t] = v;
        src ^= 1;
        __syncthreads();
    }
    if (i < n) g_rowtmp[i] = sh[src][t] - c;
    if (t == SCANB - 1) g_bsum[blockIdx.x] = sh[src][t];
}

__global__ void k_scan2(int nblk) {
    __shared__ int sh[2][128];
    int t = threadIdx.x;
    int c = (t < nblk) ? g_bsum[t] : 0;
    sh[0][t] = c;
    __syncthreads();
    int src = 0;
    for (int off = 1; off < 128; off <<= 1) {
        int v = sh[src][t];
        if (t >= off) v += sh[src][t - off];
        sh[src ^ 1][t] = v;
        src ^= 1;
        __syncthreads();
    }
    g_boff[t] = sh[src][t] - c;
}

__global__ void k_scan3(int n, int nE) {
    int i = blockIdx.x * blockDim.x + threadIdx.x;
    if (i < n) {
        int rp = g_rowtmp[i] + g_boff[i >> 10];
        g_rowptr[i] = rp;
        g_cursor[i] = rp;
    }
    if (i == 0) g_rowptr[n] = nE;
}

// counting-sort placement of packed (src, norm) records bucketed by dst
__global__ void k_fill(const void* ei, int nE) {
    int e = blockIdx.x * blockDim.x + threadIdx.x;
    if (e >= nE) return;
    int s = (int)load_index(ei, e);
    int d = (int)load_index(ei, (long long)nE + e);
    float w = g_dis[s] * g_dis[d];
    int pos = atomicAdd(&g_cursor[d], 1);
    g_csr[pos] = ((long long)__float_as_int(w) << 32) | (unsigned int)s;
}

__global__ void k_logits(const float* __restrict__ clo, const float* __restrict__ Wc,
                         const float* __restrict__ bc, const void* batch, int n) {
    int v = blockIdx.x * blockDim.x + threadIdx.x;
    if (v >= n) return;
    float l = bc[0];
#pragma unroll
    for (int j = 0; j < 8; j++) l += clo[(size_t)v * 8 + j] * Wc[j];
    g_logits[v] = l;
    int b = (int)load_index(batch, v);
    atomicAdd(&g_cnt[b], 1);
}

// ---------------- GEMM: h = act(X)@W ----------------
#define XSW(kk) ((((kk) >> 2) & 7) << 2)
#define XS(kk, rr) Xs[kk][(rr) ^ XSW(kk)]

template <int KTOT>
__global__ void __launch_bounds__(256) k_gemm(const float* __restrict__ Xparam,
                       const float* __restrict__ W,
                       const float* __restrict__ bias_in,
                       int n) {
    __shared__ float Xs[64][128];   // 32 KB
    __shared__ float Ws[64][64];    // 16 KB
    const float* X = Xparam ? Xparam : g_o;
    int tid = threadIdx.x;
    int row0 = blockIdx.x * 128;
    int lane = tid & 31;
    int wrp  = tid >> 5;
    int r0 = lane << 2;
    int c0 = wrp << 3;

    float acc[4][8];
#pragma unroll
    for (int i = 0; i < 4; i++)
#pragma unroll
        for (int j = 0; j < 8; j++) acc[i][j] = 0.f;

    for (int kc = 0; kc < KTOT; kc += 64) {
#pragma unroll
        for (int it = 0; it < 8; it++) {
            int flat = tid + it * 256;
            int r  = flat >> 4;
            int c4 = (flat & 15) << 2;
            int gr = row0 + r;
            float4 v = make_float4(0.f, 0.f, 0.f, 0.f);
            if (gr < n) v = *(const float4*)&X[(size_t)gr * KTOT + kc + c4];
            if (bias_in) {
                v.x = fmaxf(v.x + bias_in[kc + c4 + 0], 0.f);
                v.y = fmaxf(v.y + bias_in[kc + c4 + 1], 0.f);
                v.z = fmaxf(v.z + bias_in[kc + c4 + 2], 0.f);
                v.w = fmaxf(v.w + bias_in[kc + c4 + 3], 0.f);
            }
            XS(c4 + 0, r) = v.x;
            XS(c4 + 1, r) = v.y;
            XS(c4 + 2, r) = v.z;
            XS(c4 + 3, r) = v.w;
        }
#pragma unroll
        for (int it = 0; it < 4; it++) {
            int flat = tid + it * 256;
            int r  = flat >> 4;
            int c4 = (flat & 15) << 2;
            *(float4*)&Ws[r][c4] = *(const float4*)&W[(size_t)(kc + r) * 64 + c4];
        }
        __syncthreads();
#pragma unroll 8
        for (int k = 0; k < 64; k++) {
            float4 xv = *(const float4*)&Xs[k][r0 ^ XSW(k)];
            float4 w0 = *(const float4*)&Ws[k][c0];
            float4 w1 = *(const float4*)&Ws[k][c0 + 4];
            float xr[4] = {xv.x, xv.y, xv.z, xv.w};
#pragma unroll
            for (int i = 0; i < 4; i++) {
                acc[i][0] += xr[i] * w0.x; acc[i][1] += xr[i] * w0.y;
                acc[i][2] += xr[i] * w0.z; acc[i][3] += xr[i] * w0.w;
                acc[i][4] += xr[i] * w1.x; acc[i][5] += xr[i] * w1.y;
                acc[i][6] += xr[i] * w1.z; acc[i][7] += xr[i] * w1.w;
            }
        }
        __syncthreads();
    }
#pragma unroll
    for (int i = 0; i < 4; i++) {
        int gr = row0 + r0 + i;
        if (gr < n) {
            *(float4*)&g_h[(size_t)gr * 64 + c0] =
                make_float4(acc[i][0], acc[i][1], acc[i][2], acc[i][3]);
            *(float4*)&g_h[(size_t)gr * 64 + c0 + 4] =
                make_float4(acc[i][4], acc[i][5], acc[i][6], acc[i][7]);
            __half2 hp[4];
            hp[0] = __floats2half2_rn(acc[i][0], acc[i][1]);
            hp[1] = __floats2half2_rn(acc[i][2], acc[i][3]);
            hp[2] = __floats2half2_rn(acc[i][4], acc[i][5]);
            hp[3] = __floats2half2_rn(acc[i][6], acc[i][7]);
            *(uint4*)&g_hb[(size_t)gr * 32 + (c0 >> 1)] = *(uint4*)hp;
        }
    }
}

// ---------------- CSR gather aggregation: o[v] = h[v]/deg + sum_e h16[src_e]*w_e ----------------
// Warp per node; 16 lanes per edge (uint2 fp16 = 128B row), 2 edges per iteration.
// Edge record via uniform __ldg per half-warp (broadcast, no shuffles). fp32 accumulate.
__global__ void k_aggr(int n) {
    int wip  = threadIdx.x >> 5;
    int lane = threadIdx.x & 31;
    int v = blockIdx.x * 8 + wip;
    if (v >= n) return;
    int half = lane >> 4;          // which of the 2 concurrent edges
    int c4   = (lane & 15) << 2;   // feature column base (4 features/lane)
    int beg = g_rowptr[v];
    int end = g_rowptr[v + 1];

    float4 acc = make_float4(0.f, 0.f, 0.f, 0.f);
    if (half == 0) {
        float dv = g_dis[v];
        float inv = dv * dv;
        float4 sv = *(const float4*)&g_h[(size_t)v * 64 + c4];   // self term fp32
        acc.x = sv.x * inv; acc.y = sv.y * inv;
        acc.z = sv.z * inv; acc.w = sv.w * inv;
    }

#pragma unroll 4
    for (int idx = beg + half; idx < end; idx += 2) {
        long long r = __ldg(&g_csr[idx]);            // uniform across 16 lanes
        int s = (int)(r & 0xffffffffLL);
        float wt = __int_as_float((int)(r >> 32));
        uint2 u = __ldg((const uint2*)&g_hb[(size_t)s * 32 + (c4 >> 1)]);
        float2 f0 = __half22float2(*(const __half2*)&u.x);
        float2 f1 = __half22float2(*(const __half2*)&u.y);
        acc.x += f0.x * wt; acc.y += f0.y * wt;
        acc.z += f1.x * wt; acc.w += f1.y * wt;
    }

    // combine the two halves (same columns, different edge partials)
    acc.x += __shfl_xor_sync(0xffffffffu, acc.x, 16);
    acc.y += __shfl_xor_sync(0xffffffffu, acc.y, 16);
    acc.z += __shfl_xor_sync(0xffffffffu, acc.z, 16);
    acc.w += __shfl_xor_sync(0xffffffffu, acc.w, 16);
    if (half == 0)
        *(float4*)&g_o[(size_t)v * 64 + c4] = acc;
}

// ---------------- per-graph softmax pooling + MLP head ----------------
__global__ void k_pool(const float* __restrict__ b3,
                       const float* __restrict__ Wa1, const float* __restrict__ ba1,
                       const float* __restrict__ Wa2, const float* __restrict__ ba2,
                       float* __restrict__ out) {
    int b = blockIdx.x;
    int tid = threadIdx.x;
    __shared__ float red[256];
    __shared__ float ash[16];
    __shared__ int sct[2][NGR];

    int cme = g_cnt[tid];
    sct[0][tid] = cme;
    __syncthreads();
    int src = 0;
    for (int off = 1; off < NGR; off <<= 1) {
        int v = sct[src][tid];
        if (tid >= off) v += sct[src][tid - off];
        sct[src ^ 1][tid] = v;
        src ^= 1;
        __syncthreads();
    }
    int cn = g_cnt[b];
    int s0 = sct[src][b] - cn;

    float m = -3.402823466e38f;
    for (int i = tid; i < cn; i += 256) m = fmaxf(m, g_logits[s0 + i]);
    red[tid] = m; __syncthreads();
    for (int st = 128; st; st >>= 1) { if (tid < st) red[tid] = fmaxf(red[tid], red[tid + st]); __syncthreads(); }
    m = red[0]; __syncthreads();

    float z = 0.f;
    for (int i = tid; i < cn; i += 256) z += expf(g_logits[s0 + i] - m);
    red[tid] = z; __syncthreads();
    for (int st = 128; st; st >>= 1) { if (tid < st) red[tid] += red[tid + st]; __syncthreads(); }
    z = red[0]; __syncthreads();
    float invz = (cn > 0 && z > 0.f) ? 1.f / z : 0.f;

    int c = tid & 63, grp = tid >> 6;
    float bc3 = b3[c];
    float acc = 0.f;
    for (int i = grp; i < cn; i += 4) {
        int v = s0 + i;
        float w = expf(g_logits[v] - m) * invz;
        float h = fmaxf(g_o[(size_t)v * 64 + c] + bc3, 0.f);
        acc += w * h;
    }
    red[tid] = acc; __syncthreads();
    if (tid < 64) red[tid] = red[tid] + red[tid + 64] + red[tid + 128] + red[tid + 192];
    __syncthreads();

    if (tid < 16) {
        float a = ba1[tid];
#pragma unroll
        for (int k = 0; k < 64; k++) a += red[k] * Wa1[k * 16 + tid];
        ash[tid] = fmaxf(a, 0.f);
    }
    __syncthreads();
    if (tid == 0) {
        float o = ba2[0];
#pragma unroll
        for (int j = 0; j < 16; j++) o += ash[j] * Wa2[j];
        out[b] = o;
    }
}

// ---------------- launch ----------------
extern "C" void kernel_launch(void* const* d_in, const int* in_sizes, int n_in,
                              void* d_out, int out_size) {
    const float* x   = (const float*)d_in[0];
    const float* clo = (const float*)d_in[1];
    const float* W1  = (const float*)d_in[2];
    const float* b1  = (const float*)d_in[3];
    const float* W2  = (const float*)d_in[4];
    const float* b2  = (const float*)d_in[5];
    const float* W3  = (const float*)d_in[6];
    const float* b3  = (const float*)d_in[7];
    const float* Wc  = (const float*)d_in[8];
    const float* bc  = (const float*)d_in[9];
    const float* Wa1 = (const float*)d_in[10];
    const float* ba1 = (const float*)d_in[11];
    const float* Wa2 = (const float*)d_in[12];
    const float* ba2 = (const float*)d_in[13];
    const void*  ei  = d_in[14];
    const void*  bat = d_in[15];

    int n  = in_sizes[0] / 128;
    int nE = in_sizes[14] / 2;

    int nb  = (n + 255) / 256;
    int eb  = (nE + 255) / 256;
    int gb  = (n + 127) / 128;
    int scb = (n + SCANB - 1) / SCANB;
    int ab  = (n + 7) / 8;

    // One-time side-stream resources (host-side; no device memory, deterministic work).
    static cudaStream_t s2 = nullptr;
    static cudaEvent_t evFork = nullptr, evJoin = nullptr;
    if (!s2) {
        cudaStreamCreateWithFlags(&s2, cudaStreamNonBlocking);
        cudaEventCreateWithFlags(&evFork, cudaEventDisableTiming);
        cudaEventCreateWithFlags(&evJoin, cudaEventDisableTiming);
    }

    // Fork: graph-prep chain on s2, gemm<128> on the main (capture) stream.
    cudaEventRecord(evFork, 0);
    cudaStreamWaitEvent(s2, evFork, 0);

    k_detect<<<1, 256, 0, s2>>>((const unsigned int*)ei, (long long)nE * 2);
    k_init<<<nb, 256, 0, s2>>>(n);
    k_count<<<eb, 256, 0, s2>>>(ei, nE);
    k_dis_scan1<<<scb, SCANB, 0, s2>>>(n);
    k_scan2<<<1, 128, 0, s2>>>(scb);
    k_scan3<<<nb, 256, 0, s2>>>(n, nE);
    k_fill<<<eb, 256, 0, s2>>>(ei, nE);
    k_logits<<<nb, 256, 0, s2>>>(clo, Wc, bc, bat, n);
    cudaEventRecord(evJoin, s2);

    k_gemm<128><<<gb, 256>>>(x, W1, nullptr, n);   // overlaps with prep chain

    // Join: aggregation needs both g_h/g_hb (main) and CSR/dis (s2).
    cudaStreamWaitEvent(0, evJoin, 0);

    k_aggr<<<ab, 256>>>(n);
    k_gemm<64><<<gb, 256>>>(nullptr, W2, b1, n);
    k_aggr<<<ab, 256>>>(n);
    k_gemm<64><<<gb, 256>>>(nullptr, W3, b2, n);
    k_aggr<<<ab, 256>>>(n);
    k_pool<<<NGR, 256>>>(b3, Wa1, ba1, Wa2, ba2, (float*)d_out);
}

// round 7
// speedup vs baseline: 1.1593x; 1.1593x over previous
#include <cuda_runtime.h>
#include <math.h>

#define NMAX 100000
#define EMAX 1600000
#define NGR  256
#define SCANB 1024

// ---------------- device scratch (allocation-free rule: __device__ globals) ----------------
__device__ __align__(16) float g_h[(size_t)NMAX * 64];   // XW result per layer
__device__ __align__(16) float g_o[(size_t)NMAX * 64];   // aggregated output per layer
__device__ float g_deg[NMAX];
__device__ float g_dis[NMAX];
__device__ long long g_csr[EMAX];        // packed (norm<<32 | src) sorted by dst
__device__ int   g_rowptr[NMAX + 1];
__device__ int   g_cursor[NMAX];
__device__ int   g_rowtmp[NMAX];
__device__ int   g_bsum[128];
__device__ int   g_boff[128];
__device__ float g_logits[NMAX];
__device__ int   g_cnt[NGR];
__device__ int   g_is64;

// ---------------- int64/int32 index abstraction ----------------
__device__ __forceinline__ long long load_index(const void* p, long long i) {
    if (g_is64) return ((const long long*)p)[i];
    return (long long)((const int*)p)[i];
}

__global__ void k_detect(const unsigned int* w, long long nvals) {
    __shared__ int any;
    if (threadIdx.x == 0) any = 0;
    __syncthreads();
    long long lim = nvals < 512 ? nvals : 512;
    for (long long i = threadIdx.x; i < lim; i += blockDim.x)
        if (w[2 * i + 1] != 0u) any = 1;
    __syncthreads();
    if (threadIdx.x == 0) g_is64 = (any == 0) ? 1 : 0;
}

__global__ void k_init(int n) {
    int i = blockIdx.x * blockDim.x + threadIdx.x;
    if (i < n) g_deg[i] = 1.0f;   // self loop
    if (i < NGR) g_cnt[i] = 0;
}

__global__ void k_count(const void* ei, int nE) {
    int e = blockIdx.x * blockDim.x + threadIdx.x;
    if (e >= nE) return;
    int d = (int)load_index(ei, (long long)nE + e);
    atomicAdd(&g_deg[d], 1.0f);
}

__global__ void k_dis_scan1(int n) {
    __shared__ int sh[2][SCANB];
    int t = threadIdx.x;
    int i = blockIdx.x * SCANB + t;
    int c = 0;
    if (i < n) {
        float dv = g_deg[i];
        g_dis[i] = rsqrtf(dv);
        c = (int)dv - 1;
    }
    sh[0][t] = c;
    __syncthreads();
    int src = 0;
    for (int off = 1; off < SCANB; off <<= 1) {
        int v = sh[src][t];
        if (t >= off) v += sh[src][t - off];
        sh[src ^ 1][t] = v;
        src ^= 1;
        __syncthreads();
    }
    if (i < n) g_rowtmp[i] = sh[src][t] - c;
    if (t == SCANB - 1) g_bsum[blockIdx.x] = sh[src][t];
}

__global__ void k_scan2(int nblk) {
    __shared__ int sh[2][128];
    int t = threadIdx.x;
    int c = (t < nblk) ? g_bsum[t] : 0;
    sh[0][t] = c;
    __syncthreads();
    int src = 0;
    for (int off = 1; off < 128; off <<= 1) {
        int v = sh[src][t];
        if (t >= off) v += sh[src][t - off];
        sh[src ^ 1][t] = v;
        src ^= 1;
        __syncthreads();
    }
    g_boff[t] = sh[src][t] - c;
}

__global__ void k_scan3(int n, int nE) {
    int i = blockIdx.x * blockDim.x + threadIdx.x;
    if (i < n) {
        int rp = g_rowtmp[i] + g_boff[i >> 10];
        g_rowptr[i] = rp;
        g_cursor[i] = rp;
    }
    if (i == 0) g_rowptr[n] = nE;
}

__global__ void k_fill(const void* ei, int nE) {
    int e = blockIdx.x * blockDim.x + threadIdx.x;
    if (e >= nE) return;
    int s = (int)load_index(ei, e);
    int d = (int)load_index(ei, (long long)nE + e);
    float w = g_dis[s] * g_dis[d];
    int pos = atomicAdd(&g_cursor[d], 1);
    g_csr[pos] = ((long long)__float_as_int(w) << 32) | (unsigned int)s;
}

__global__ void k_logits(const float* __restrict__ clo, const float* __restrict__ Wc,
                         const float* __restrict__ bc, const void* batch, int n) {
    int v = blockIdx.x * blockDim.x + threadIdx.x;
    if (v >= n) return;
    float l = bc[0];
#pragma unroll
    for (int j = 0; j < 8; j++) l += clo[(size_t)v * 8 + j] * Wc[j];
    g_logits[v] = l;
    int b = (int)load_index(batch, v);
    atomicAdd(&g_cnt[b], 1);
}

// ---------------- tf32 tensor-core GEMM (3xTF32, fp32-accurate): h = act(X)@W ----------------
__device__ __forceinline__ void mma_tf32(float* d, const unsigned* a, const unsigned* b) {
    asm volatile(
        "mma.sync.aligned.m16n8k8.row.col.f32.tf32.tf32.f32 "
        "{%0,%1,%2,%3}, {%4,%5,%6,%7}, {%8,%9}, {%0,%1,%2,%3};\n"
        : "+f"(d[0]), "+f"(d[1]), "+f"(d[2]), "+f"(d[3])
        : "r"(a[0]), "r"(a[1]), "r"(a[2]), "r"(a[3]), "r"(b[0]), "r"(b[1]));
}

__device__ __forceinline__ void split_tf32(float x, unsigned& hi, unsigned& lo) {
    unsigned h;
    asm("cvt.rna.tf32.f32 %0, %1;" : "=r"(h) : "f"(x));
    hi = h;
    float res = x - __uint_as_float(h);
    unsigned l;
    asm("cvt.rna.tf32.f32 %0, %1;" : "=r"(l) : "f"(res));
    lo = l;
}

// Block: 128 rows x 64 cols, 8 warps (4x2 warp grid), warp tile 32x32 (2x4 m16n8k8).
// K-chunk 32 in smem. Pads: Xs stride 36 (banks 4r+c bijective), Ws stride 72 (8k+n bijective).
template <int KTOT>
__global__ void __launch_bounds__(256) k_gemm(const float* __restrict__ Xparam,
                       const float* __restrict__ W,
                       const float* __restrict__ bias_in,
                       int n) {
    __shared__ float Xs[128][36];   // 18 KB
    __shared__ float Ws[32][72];    //  9 KB
    const float* X = Xparam ? Xparam : g_o;
    int tid  = threadIdx.x;
    int lane = tid & 31;
    int wid  = tid >> 5;
    int row0 = blockIdx.x * 128;
    int wm = (wid & 3) << 5;    // 0,32,64,96
    int wn = (wid >> 2) << 5;   // 0,32

    float acc[2][4][4];
#pragma unroll
    for (int mt = 0; mt < 2; mt++)
#pragma unroll
        for (int nt = 0; nt < 4; nt++)
#pragma unroll
            for (int f = 0; f < 4; f++) acc[mt][nt][f] = 0.f;

    for (int kc = 0; kc < KTOT; kc += 32) {
        // X tile: 128 x 32 (4 float4/thread)
#pragma unroll
        for (int it = 0; it < 4; it++) {
            int slot = tid + it * 256;      // 0..1023
            int r  = slot >> 3;             // 0..127
            int c4 = (slot & 7) << 2;       // 0..28
            int gr = row0 + r;
            float4 v = make_float4(0.f, 0.f, 0.f, 0.f);
            if (gr < n) v = *(const float4*)&X[(size_t)gr * KTOT + kc + c4];
            if (bias_in) {
                v.x = fmaxf(v.x + bias_in[kc + c4 + 0], 0.f);
                v.y = fmaxf(v.y + bias_in[kc + c4 + 1], 0.f);
                v.z = fmaxf(v.z + bias_in[kc + c4 + 2], 0.f);
                v.w = fmaxf(v.w + bias_in[kc + c4 + 3], 0.f);
            }
            *(float4*)&Xs[r][c4] = v;
        }
        // W chunk: 32 x 64 (2 float4/thread)
#pragma unroll
        for (int it = 0; it < 2; it++) {
            int slot = tid + it * 256;      // 0..511
            int r  = slot >> 4;             // 0..31
            int c4 = (slot & 15) << 2;
            *(float4*)&Ws[r][c4] = *(const float4*)&W[(size_t)(kc + r) * 64 + c4];
        }
        __syncthreads();

#pragma unroll
        for (int ks = 0; ks < 32; ks += 8) {
            unsigned ahi[2][4], alo[2][4], bhi[4][2], blo[4][2];
#pragma unroll
            for (int mt = 0; mt < 2; mt++) {
                int rb = wm + mt * 16 + (lane >> 2);
                int cc = ks + (lane & 3);
                split_tf32(Xs[rb][cc],         ahi[mt][0], alo[mt][0]);
                split_tf32(Xs[rb + 8][cc],     ahi[mt][1], alo[mt][1]);
                split_tf32(Xs[rb][cc + 4],     ahi[mt][2], alo[mt][2]);
                split_tf32(Xs[rb + 8][cc + 4], ahi[mt][3], alo[mt][3]);
            }
#pragma unroll
            for (int nt = 0; nt < 4; nt++) {
                int nb = wn + nt * 8 + (lane >> 2);
                int kr = ks + (lane & 3);
                split_tf32(Ws[kr][nb],     bhi[nt][0], blo[nt][0]);
                split_tf32(Ws[kr + 4][nb], bhi[nt][1], blo[nt][1]);
            }
#pragma unroll
            for (int mt = 0; mt < 2; mt++)
#pragma unroll
                for (int nt = 0; nt < 4; nt++) {
                    mma_tf32(acc[mt][nt], ahi[mt], bhi[nt]);
                    mma_tf32(acc[mt][nt], ahi[mt], blo[nt]);
                    mma_tf32(acc[mt][nt], alo[mt], bhi[nt]);
                }
        }
        __syncthreads();
    }

    // epilogue: D fragment (mt,nt): rows wm+mt*16+(lane>>2) (+8), cols wn+nt*8+2*(lane&3) (+1)
#pragma unroll
    for (int mt = 0; mt < 2; mt++) {
        int r1 = row0 + wm + mt * 16 + (lane >> 2);
        int r2 = r1 + 8;
#pragma unroll
        for (int nt = 0; nt < 4; nt++) {
            int cb = wn + nt * 8 + ((lane & 3) << 1);
            if (r1 < n)
                *(float2*)&g_h[(size_t)r1 * 64 + cb] = make_float2(acc[mt][nt][0], acc[mt][nt][1]);
            if (r2 < n)
                *(float2*)&g_h[(size_t)r2 * 64 + cb] = make_float2(acc[mt][nt][2], acc[mt][nt][3]);
        }
    }
}

// ---------------- CSR gather aggregation: o[v] = h[v]/deg + sum_e h[src_e]*w_e ----------------
// Warp per node; 16 lanes per edge (float4/lane = 256B row), 2 edges per iteration.
__global__ void k_aggr(int n) {
    int wip  = threadIdx.x >> 5;
    int lane = threadIdx.x & 31;
    int v = blockIdx.x * 8 + wip;
    if (v >= n) return;
    int half = lane >> 4;
    int c4   = (lane & 15) << 2;
    int beg = g_rowptr[v];
    int end = g_rowptr[v + 1];

    float4 acc = make_float4(0.f, 0.f, 0.f, 0.f);
    if (half == 0) {
        float dv = g_dis[v];
        float inv = dv * dv;
        float4 sv = *(const float4*)&g_h[(size_t)v * 64 + c4];
        acc.x = sv.x * inv; acc.y = sv.y * inv;
        acc.z = sv.z * inv; acc.w = sv.w * inv;
    }

#pragma unroll 4
    for (int idx = beg + half; idx < end; idx += 2) {
        long long r = __ldg(&g_csr[idx]);            // uniform across 16 lanes
        int s = (int)(r & 0xffffffffLL);
        float wt = __int_as_float((int)(r >> 32));
        float4 hv = __ldg((const float4*)&g_h[(size_t)s * 64 + c4]);
        acc.x += hv.x * wt; acc.y += hv.y * wt;
        acc.z += hv.z * wt; acc.w += hv.w * wt;
    }

    acc.x += __shfl_xor_sync(0xffffffffu, acc.x, 16);
    acc.y += __shfl_xor_sync(0xffffffffu, acc.y, 16);
    acc.z += __shfl_xor_sync(0xffffffffu, acc.z, 16);
    acc.w += __shfl_xor_sync(0xffffffffu, acc.w, 16);
    if (half == 0)
        *(float4*)&g_o[(size_t)v * 64 + c4] = acc;
}

// ---------------- per-graph softmax pooling + MLP head ----------------
__global__ void k_pool(const float* __restrict__ b3,
                       const float* __restrict__ Wa1, const float* __restrict__ ba1,
                       const float* __restrict__ Wa2, const float* __restrict__ ba2,
                       float* __restrict__ out) {
    int b = blockIdx.x;
    int tid = threadIdx.x;
    __shared__ float red[256];
    __shared__ float ash[16];
    __shared__ int sct[2][NGR];

    int cme = g_cnt[tid];
    sct[0][tid] = cme;
    __syncthreads();
    int src = 0;
    for (int off = 1; off < NGR; off <<= 1) {
        int v = sct[src][tid];
        if (tid >= off) v += sct[src][tid - off];
        sct[src ^ 1][tid] = v;
        src ^= 1;
        __syncthreads();
    }
    int cn = g_cnt[b];
    int s0 = sct[src][b] - cn;

    float m = -3.402823466e38f;
    for (int i = tid; i < cn; i += 256) m = fmaxf(m, g_logits[s0 + i]);
    red[tid] = m; __syncthreads();
    for (int st = 128; st; st >>= 1) { if (tid < st) red[tid] = fmaxf(red[tid], red[tid + st]); __syncthreads(); }
    m = red[0]; __syncthreads();

    float z = 0.f;
    for (int i = tid; i < cn; i += 256) z += expf(g_logits[s0 + i] - m);
    red[tid] = z; __syncthreads();
    for (int st = 128; st; st >>= 1) { if (tid < st) red[tid] += red[tid + st]; __syncthreads(); }
    z = red[0]; __syncthreads();
    float invz = (cn > 0 && z > 0.f) ? 1.f / z : 0.f;

    int c = tid & 63, grp = tid >> 6;
    float bc3 = b3[c];
    float acc = 0.f;
    for (int i = grp; i < cn; i += 4) {
        int v = s0 + i;
        float w = expf(g_logits[v] - m) * invz;
        float h = fmaxf(g_o[(size_t)v * 64 + c] + bc3, 0.f);
        acc += w * h;
    }
    red[tid] = acc; __syncthreads();
    if (tid < 64) red[tid] = red[tid] + red[tid + 64] + red[tid + 128] + red[tid + 192];
    __syncthreads();

    if (tid < 16) {
        float a = ba1[tid];
#pragma unroll
        for (int k = 0; k < 64; k++) a += red[k] * Wa1[k * 16 + tid];
        ash[tid] = fmaxf(a, 0.f);
    }
    __syncthreads();
    if (tid == 0) {
        float o = ba2[0];
#pragma unroll
        for (int j = 0; j < 16; j++) o += ash[j] * Wa2[j];
        out[b] = o;
    }
}

// ---------------- launch ----------------
extern "C" void kernel_launch(void* const* d_in, const int* in_sizes, int n_in,
                              void* d_out, int out_size) {
    const float* x   = (const float*)d_in[0];
    const float* clo = (const float*)d_in[1];
    const float* W1  = (const float*)d_in[2];
    const float* b1  = (const float*)d_in[3];
    const float* W2  = (const float*)d_in[4];
    const float* b2  = (const float*)d_in[5];
    const float* W3  = (const float*)d_in[6];
    const float* b3  = (const float*)d_in[7];
    const float* Wc  = (const float*)d_in[8];
    const float* bc  = (const float*)d_in[9];
    const float* Wa1 = (const float*)d_in[10];
    const float* ba1 = (const float*)d_in[11];
    const float* Wa2 = (const float*)d_in[12];
    const float* ba2 = (const float*)d_in[13];
    const void*  ei  = d_in[14];
    const void*  bat = d_in[15];

    int n  = in_sizes[0] / 128;
    int nE = in_sizes[14] / 2;

    int nb  = (n + 255) / 256;
    int eb  = (nE + 255) / 256;
    int gb  = (n + 127) / 128;
    int scb = (n + SCANB - 1) / SCANB;
    int ab  = (n + 7) / 8;

    static cudaStream_t s2 = nullptr;
    static cudaEvent_t evFork = nullptr, evJoin = nullptr;
    if (!s2) {
        cudaStreamCreateWithFlags(&s2, cudaStreamNonBlocking);
        cudaEventCreateWithFlags(&evFork, cudaEventDisableTiming);
        cudaEventCreateWithFlags(&evJoin, cudaEventDisableTiming);
    }

    // Fork: graph-prep chain on s2, gemm<128> on the main (capture) stream.
    cudaEventRecord(evFork, 0);
    cudaStreamWaitEvent(s2, evFork, 0);

    k_detect<<<1, 256, 0, s2>>>((const unsigned int*)ei, (long long)nE * 2);
    k_init<<<nb, 256, 0, s2>>>(n);
    k_count<<<eb, 256, 0, s2>>>(ei, nE);
    k_dis_scan1<<<scb, SCANB, 0, s2>>>(n);
    k_scan2<<<1, 128, 0, s2>>>(scb);
    k_scan3<<<nb, 256, 0, s2>>>(n, nE);
    k_fill<<<eb, 256, 0, s2>>>(ei, nE);
    k_logits<<<nb, 256, 0, s2>>>(clo, Wc, bc, bat, n);
    cudaEventRecord(evJoin, s2);

    k_gemm<128><<<gb, 256>>>(x, W1, nullptr, n);   // overlaps with prep chain

    cudaStreamWaitEvent(0, evJoin, 0);

    k_aggr<<<ab, 256>>>(n);
    k_gemm<64><<<gb, 256>>>(nullptr, W2, b1, n);
    k_aggr<<<ab, 256>>>(n);
    k_gemm<64><<<gb, 256>>>(nullptr, W3, b2, n);
    k_aggr<<<ab, 256>>>(n);
    k_pool<<<NGR, 256>>>(b3, Wa1, ba1, Wa2, ba2, (float*)d_out);
}